// round 14
// baseline (speedup 1.0000x reference)
#include <cuda_runtime.h>
#include <cstdint>
#include <cfloat>

// Sparsemax (d = 4096), Michelot with single-pass per-warp compaction.
//
//   Pass 1: load row (streaming) -> s_row; per-warp max m_w (REDUX);
//           compact {v > m_w - 1} -> s_buf (atomic cursor).  [barrier A]
//   Warp 0: M = block max; tau = M-1. Michelot over s_buf: since
//           tau_1 > M-1 and tau is non-decreasing, candidates from weaker
//           warp seeds (<= M-1) are never counted — no filtering needed.
//           n<=128: candidates in 4 regs/lane, shuffle-only iterations.
//           Fallback scans s_buf / s_row (degenerate rows).  [barrier B]
//   Epilogue: out = max(row - tau, 0) from SMEM.
//
// Row staged in SMEM => 32 regs => 8 CTAs/SM. One LDS row-pass and one
// block barrier fewer than the R12 kernel.

#define ROW_D     4096
#define THREADS   256
#define NW        (THREADS / 32)
#define V4_PER_T  4
#define CAND_MAX  512

__device__ __forceinline__ unsigned f2key(float f) {
    const unsigned b = __float_as_uint(f);
    return b ^ ((unsigned)((int)b >> 31) | 0x80000000u);
}
__device__ __forceinline__ float key2f(unsigned k) {
    return __uint_as_float(k ^ ((unsigned)((int)(~k) >> 31) | 0x80000000u));
}

__global__ __launch_bounds__(THREADS, 8)
void sparsemax_kernel(const float* __restrict__ x, float* __restrict__ out)
{
    __shared__ float  s_max[NW];
    __shared__ int    s_n;
    __shared__ float  s_tau;
    __shared__ float  s_buf[CAND_MAX];
    __shared__ float4 s_row[ROW_D / 4];   // 16 KB: the whole row

    const size_t row_base = (size_t)blockIdx.x * ROW_D;
    const float4* __restrict__ xr  = reinterpret_cast<const float4*>(x + row_base);
    float4*       __restrict__ orr = reinterpret_cast<float4*>(out + row_base);

    const int tid = threadIdx.x;
    const int wid = tid >> 5;
    const int lid = tid & 31;

    // ---- issue row loads, then a (nearly free) init barrier ----
    float4 v[V4_PER_T];
#pragma unroll
    for (int i = 0; i < V4_PER_T; ++i)
        v[i] = __ldcs(&xr[tid + i * THREADS]);
    if (tid == 0) s_n = 0;
    __syncthreads();                  // no warp skew yet: ~free

    // ---- per-warp max, stash row, compact per-warp survivors ----
    float m = -FLT_MAX;
#pragma unroll
    for (int i = 0; i < V4_PER_T; ++i) {
        const float4 q = v[i];
        m = fmaxf(m, fmaxf(fmaxf(q.x, q.y), fmaxf(q.z, q.w)));
        s_row[tid + i * THREADS] = q;
    }
    m = key2f(__reduce_max_sync(0xFFFFFFFFu, f2key(m)));
    const float thrw = m - 1.0f;      // <= M-1 <= tau*: per-warp superset

    int myc = 0;
#pragma unroll
    for (int i = 0; i < V4_PER_T; ++i) {
        const float4 q = v[i];
        myc += (q.x > thrw) + (q.y > thrw) + (q.z > thrw) + (q.w > thrw);
    }
    if (myc > 0) {
        int pos = atomicAdd(&s_n, myc);
#pragma unroll
        for (int i = 0; i < V4_PER_T; ++i) {
            const float4 q = v[i];
            if (q.x > thrw) { if (pos < CAND_MAX) s_buf[pos] = q.x; ++pos; }
            if (q.y > thrw) { if (pos < CAND_MAX) s_buf[pos] = q.y; ++pos; }
            if (q.z > thrw) { if (pos < CAND_MAX) s_buf[pos] = q.z; ++pos; }
            if (q.w > thrw) { if (pos < CAND_MAX) s_buf[pos] = q.w; ++pos; }
        }
    }
    if (lid == 0) s_max[wid] = m;
    __syncthreads();                  // barrier A

    // ---- warp 0: Michelot over candidates, starting at tau = M-1 ----
    if (wid == 0) {
        float M = s_max[0];
#pragma unroll
        for (int w = 1; w < NW; ++w) M = fmaxf(M, s_max[w]);
        const int n = s_n;

        float tau  = M - 1.0f;        // tau_1 > M-1; tau non-decreasing =>
        int   prev = -1;              // sub-threshold candidates never count

        if (n <= 128) {
            // common case: candidates in 4 regs/lane; shuffle-only loop
            float r0 = (lid       < n) ? s_buf[lid]       : -FLT_MAX;
            float r1 = (lid + 32  < n) ? s_buf[lid + 32]  : -FLT_MAX;
            float r2 = (lid + 64  < n) ? s_buf[lid + 64]  : -FLT_MAX;
            float r3 = (lid + 96  < n) ? s_buf[lid + 96]  : -FLT_MAX;

            for (int iter = 0; iter < 64; ++iter) {
                float ls = 0.0f;
                int   lc = 0;
                if (r0 > tau) { ls += r0; ++lc; }
                if (r1 > tau) { ls += r1; ++lc; }
                if (r2 > tau) { ls += r2; ++lc; }
                if (r3 > tau) { ls += r3; ++lc; }
#pragma unroll
                for (int o = 16; o > 0; o >>= 1)
                    ls += __shfl_xor_sync(0xFFFFFFFFu, ls, o);
                lc = __reduce_add_sync(0xFFFFFFFFu, lc);

                tau = (ls - 1.0f) / (float)lc;   // lc >= 1: row max > tau
                if (lc == prev) break;           // fixed point -> tau = tau*
                prev = lc;
            }
        } else {
            const bool overflow = (n > CAND_MAX);      // degenerate rows only
            const float* __restrict__ src = overflow
                ? reinterpret_cast<const float*>(s_row) : s_buf;
            const int nn = overflow ? ROW_D : n;

            for (int iter = 0; iter < 64; ++iter) {
                float ls = 0.0f;
                int   lc = 0;
                for (int j = lid; j < nn; j += 32) {
                    const float vv = src[j];
                    if (vv > tau) { ls += vv; ++lc; }
                }
#pragma unroll
                for (int o = 16; o > 0; o >>= 1)
                    ls += __shfl_xor_sync(0xFFFFFFFFu, ls, o);
                lc = __reduce_add_sync(0xFFFFFFFFu, lc);

                tau = (ls - 1.0f) / (float)lc;
                if (lc == prev) break;
                prev = lc;
            }
        }
        if (lid == 0) s_tau = tau;
    }
    __syncthreads();                  // barrier B
    const float tau = s_tau;

    // ---- epilogue: out = max(row - tau, 0) from SMEM ----
#pragma unroll
    for (int i = 0; i < V4_PER_T; ++i) {
        const float4 q = s_row[tid + i * THREADS];
        float4 o;
        o.x = fmaxf(q.x - tau, 0.0f);
        o.y = fmaxf(q.y - tau, 0.0f);
        o.z = fmaxf(q.z - tau, 0.0f);
        o.w = fmaxf(q.w - tau, 0.0f);
        __stcs(&orr[tid + i * THREADS], o);
    }
}

extern "C" void kernel_launch(void* const* d_in, const int* in_sizes, int n_in,
                              void* d_out, int out_size)
{
    const float* x   = (const float*)d_in[0];
    float*       out = (float*)d_out;
    const int n_rows = in_sizes[0] / ROW_D;   // 16384
    sparsemax_kernel<<<n_rows, THREADS>>>(x, out);
}

// round 15
// speedup vs baseline: 1.0250x; 1.0250x over previous
#include <cuda_runtime.h>
#include <cstdint>
#include <cfloat>

// Sparsemax (d = 4096), max-seeded Michelot, row staged in SMEM (8 CTAs/SM).
// (R12 structure — best measured — with an n<=32 single-register tail path.)
//
//   Pass 1: load row (streaming), per-warp max, stash row -> s_row. [bar 1]
//   Block max M; thr0 = M-1 (tau* >= M-1 => survivors superset of support).
//   Pass 2: re-read row from SMEM, compact survivors -> s_buf.      [bar 2]
//   Warp 0: Michelot on the ~16 candidates; n<=32 keeps them in ONE
//           register/lane (n<=64: two), shuffle-only iterations.
//           Fallback scans s_buf / s_row (degenerate rows).         [bar 3]
//   Epilogue: out = max(row - tau, 0) from SMEM.

#define ROW_D     4096
#define THREADS   256
#define NW        (THREADS / 32)
#define V4_PER_T  4
#define CAND_MAX  512

__device__ __forceinline__ unsigned f2key(float f) {
    const unsigned b = __float_as_uint(f);
    return b ^ ((unsigned)((int)b >> 31) | 0x80000000u);
}
__device__ __forceinline__ float key2f(unsigned k) {
    return __uint_as_float(k ^ ((unsigned)((int)(~k) >> 31) | 0x80000000u));
}

__global__ __launch_bounds__(THREADS, 8)
void sparsemax_kernel(const float* __restrict__ x, float* __restrict__ out)
{
    __shared__ float  s_max[NW];
    __shared__ int    s_n;
    __shared__ float  s_tau;
    __shared__ float  s_buf[CAND_MAX];
    __shared__ float4 s_row[ROW_D / 4];   // 16 KB: the whole row

    const size_t row_base = (size_t)blockIdx.x * ROW_D;
    const float4* __restrict__ xr  = reinterpret_cast<const float4*>(x + row_base);
    float4*       __restrict__ orr = reinterpret_cast<float4*>(out + row_base);

    const int tid = threadIdx.x;
    const int wid = tid >> 5;
    const int lid = tid & 31;

    // ---- pass 1: load row, track max, stash to SMEM ----
    float m = -FLT_MAX;
#pragma unroll
    for (int i = 0; i < V4_PER_T; ++i) {
        const float4 q = __ldcs(&xr[tid + i * THREADS]);
        m = fmaxf(m, fmaxf(fmaxf(q.x, q.y), fmaxf(q.z, q.w)));
        s_row[tid + i * THREADS] = q;
    }
    m = key2f(__reduce_max_sync(0xFFFFFFFFu, f2key(m)));
    if (lid == 0) s_max[wid] = m;
    if (tid == 0) s_n = 0;
    __syncthreads();                                   // barrier 1

    float M = s_max[0];
#pragma unroll
    for (int w = 1; w < NW; ++w) M = fmaxf(M, s_max[w]);
    const float thr0 = M - 1.0f;                       // <= tau*

    // ---- pass 2: compact survivors (values re-read from SMEM) ----
    int myc = 0;
#pragma unroll
    for (int i = 0; i < V4_PER_T; ++i) {
        const float4 q = s_row[tid + i * THREADS];
        myc += (q.x > thr0) + (q.y > thr0) + (q.z > thr0) + (q.w > thr0);
    }
    if (myc > 0) {
        int pos = atomicAdd(&s_n, myc);
#pragma unroll
        for (int i = 0; i < V4_PER_T; ++i) {
            const float4 q = s_row[tid + i * THREADS];
            if (q.x > thr0) { if (pos < CAND_MAX) s_buf[pos] = q.x; ++pos; }
            if (q.y > thr0) { if (pos < CAND_MAX) s_buf[pos] = q.y; ++pos; }
            if (q.z > thr0) { if (pos < CAND_MAX) s_buf[pos] = q.z; ++pos; }
            if (q.w > thr0) { if (pos < CAND_MAX) s_buf[pos] = q.w; ++pos; }
        }
    }
    __syncthreads();                                   // barrier 2

    // ---- warp 0: Michelot over candidates ----
    if (wid == 0) {
        const int n = s_n;
        float tau  = thr0;     // first pass reproduces iter-1 over survivors
        int   prev = -1;

        if (n <= 32) {
            // dominant case (~16 candidates): ONE register per lane
            const float r0 = (lid < n) ? s_buf[lid] : -FLT_MAX;
            for (int iter = 0; iter < 64; ++iter) {
                float ls = 0.0f;
                int   lc = 0;
                if (r0 > tau) { ls = r0; lc = 1; }
#pragma unroll
                for (int o = 16; o > 0; o >>= 1)
                    ls += __shfl_xor_sync(0xFFFFFFFFu, ls, o);
                lc = __reduce_add_sync(0xFFFFFFFFu, lc);

                tau = (ls - 1.0f) / (float)lc;   // lc >= 1: row max > tau
                if (lc == prev) break;           // fixed point -> tau = tau*
                prev = lc;
            }
        } else if (n <= 64) {
            const float r0 = s_buf[lid];         // n > 32: lane's first slot valid
            const float r1 = (lid + 32 < n) ? s_buf[lid + 32] : -FLT_MAX;
            for (int iter = 0; iter < 64; ++iter) {
                float ls = 0.0f;
                int   lc = 0;
                if (r0 > tau) { ls += r0; ++lc; }
                if (r1 > tau) { ls += r1; ++lc; }
#pragma unroll
                for (int o = 16; o > 0; o >>= 1)
                    ls += __shfl_xor_sync(0xFFFFFFFFu, ls, o);
                lc = __reduce_add_sync(0xFFFFFFFFu, lc);

                tau = (ls - 1.0f) / (float)lc;
                if (lc == prev) break;
                prev = lc;
            }
        } else {
            const bool overflow = (n > CAND_MAX);      // degenerate rows only
            const float* __restrict__ src = overflow
                ? reinterpret_cast<const float*>(s_row) : s_buf;
            const int nn = overflow ? ROW_D : n;

            for (int iter = 0; iter < 64; ++iter) {
                float ls = 0.0f;
                int   lc = 0;
                for (int j = lid; j < nn; j += 32) {
                    const float vv = src[j];
                    if (vv > tau) { ls += vv; ++lc; }
                }
#pragma unroll
                for (int o = 16; o > 0; o >>= 1)
                    ls += __shfl_xor_sync(0xFFFFFFFFu, ls, o);
                lc = __reduce_add_sync(0xFFFFFFFFu, lc);

                tau = (ls - 1.0f) / (float)lc;
                if (lc == prev) break;
                prev = lc;
            }
        }
        if (lid == 0) s_tau = tau;
    }
    __syncthreads();                                   // barrier 3
    const float tau = s_tau;

    // ---- epilogue: out = max(row - tau, 0) from SMEM ----
#pragma unroll
    for (int i = 0; i < V4_PER_T; ++i) {
        const float4 q = s_row[tid + i * THREADS];
        float4 o;
        o.x = fmaxf(q.x - tau, 0.0f);
        o.y = fmaxf(q.y - tau, 0.0f);
        o.z = fmaxf(q.z - tau, 0.0f);
        o.w = fmaxf(q.w - tau, 0.0f);
        __stcs(&orr[tid + i * THREADS], o);
    }
}

extern "C" void kernel_launch(void* const* d_in, const int* in_sizes, int n_in,
                              void* d_out, int out_size)
{
    const float* x   = (const float*)d_in[0];
    float*       out = (float*)d_out;
    const int n_rows = in_sizes[0] / ROW_D;   // 16384
    sparsemax_kernel<<<n_rows, THREADS>>>(x, out);
}